// round 9
// baseline (speedup 1.0000x reference)
#include <cuda_runtime.h>

// GarNet: B=256, V=1024, F=16, P=16, A=8, NF=32
// out[b,v,n] = mask(v) * ( sum_a ew[v,a] * M[b,a,n] + b_out[n] )
//   ew[v,a]  = mask(v) * 2^(-(data[v]·W_s + b_s)[a])
//   agg[a,p] = (1/V) sum_v ew[v,a] * (data[v]·W_flr + b_flr)[p]
//   M[a,n]   = sum_p agg[a,p] * W_out[a*P+p, n]
//
// FUSED single-pass kernel (grid 8x256, 128t):
//   phase 1: feat+ew (f32x2, constant-port weights), ew stays in smem,
//            quad-product block reduction -> g_part; last block per batch
//            computes agg -> M -> g_M and release-sets flag[b].
//   phase 2: spin-acquire flag[b], epilogue from in-smem ew tile,
//            TMA bulk store of the 16KB output tile.

#define NB   256
#define NV   1024
#define NFEA 16
#define NP   16
#define NA   8
#define NOUT 32

#define K1S  8
#define K1V  128

#define RS   130      // ull stride per pair-row (128 + 2)

__device__ float g_part[NB * K1S * 128];      // 1 MB
__device__ float g_M[NB * NA * NOUT];         // 256 KB
__device__ float g_wpack[408];
__device__ unsigned int g_cnt[NB];            // zero-init
__device__ unsigned int g_done[NB];           // zero-init
__device__ int          g_flag[NB];           // zero-init

// packed weights: [0,256) W_flr, [256,384) W_s, [384,400) b_flr, [400,408) b_s
__constant__ __align__(16) float c_pack[408];

#define FMA_F32X2(d, a, b, c) \
    asm("fma.rn.f32x2 %0, %1, %2, %3;" : "=l"(d) : "l"(a), "l"(b), "l"(c))
#define PACK2_SAME(out, x) \
    asm("mov.b64 %0, {%1, %1};" : "=l"(out) : "r"(__float_as_uint(x)))
#define PACK2(out, lo, hi) \
    asm("mov.b64 %0, {%1, %2};" : "=l"(out) : "r"(__float_as_uint(lo)), "r"(__float_as_uint(hi)))
#define UNPACK2(lo, hi, in) \
    asm("mov.b64 {%0, %1}, %2;" : "=r"(lo), "=r"(hi) : "l"(in))

#define BULK_S2G(gptr, saddr, bytes) \
    asm volatile("cp.async.bulk.global.shared::cta.bulk_group [%0], [%1], %2;" \
                 :: "l"(gptr), "r"(saddr), "r"(bytes) : "memory")
#define BULK_COMMIT() \
    asm volatile("cp.async.bulk.commit_group;" ::: "memory")
#define BULK_WAIT0() \
    asm volatile("cp.async.bulk.wait_group 0;" ::: "memory")
#define FENCE_ASYNC() \
    asm volatile("fence.proxy.async.shared::cta;" ::: "memory")

// ==================== Kp: pack weights into staging ====================
__global__ void __launch_bounds__(128)
garnet_kp(const float* __restrict__ W_flr,
          const float* __restrict__ W_s,
          const float* __restrict__ b_flr,
          const float* __restrict__ b_s)
{
    const int t = threadIdx.x;
    g_wpack[t]       = W_flr[t];
    g_wpack[t + 128] = W_flr[t + 128];
    g_wpack[t + 256] = W_s[t];
    if (t < 16) g_wpack[384 + t] = b_flr[t];
    if (t < 8)  g_wpack[400 + t] = b_s[t];
}

// ==================== fused kernel ====================
__global__ void __launch_bounds__(128)
garnet_fused(const float* __restrict__ data,
             const int*   __restrict__ num_vertex,
             const float* __restrict__ W_out,
             const float* __restrict__ b_out,
             float*       __restrict__ out)
{
    // smem: [0,16384) red2 (phase1) / otile (phase2, aliased)
    //       [16384,18432) comb / agg_sh    [18432,22528) ewt
    __shared__ __align__(16) unsigned char smem_raw[16384 + 2048 + 4096];
    unsigned long long* red2 = reinterpret_cast<unsigned long long*>(smem_raw);
    float4*  otile  = reinterpret_cast<float4*>(smem_raw);
    unsigned long long* comb = reinterpret_cast<unsigned long long*>(smem_raw + 16384);
    float*   agg_sh = reinterpret_cast<float*>(smem_raw + 16384);
    float4*  ewt    = reinterpret_cast<float4*>(smem_raw + 16384 + 2048);
    __shared__ int s_tail;

    const int t = threadIdx.x;
    const int s = blockIdx.x;      // 0..7
    const int b = blockIdx.y;
    const int v = s * K1V + t;

    // ---------------- phase 1: feat + ew ----------------
    const float4* d4 = reinterpret_cast<const float4*>(data) + ((size_t)b * NV + v) * 4;
    float4 q0 = d4[0], q1 = d4[1], q2 = d4[2], q3 = d4[3];
    const int nv = num_vertex[b];

    float xv[16] = {q0.x,q0.y,q0.z,q0.w, q1.x,q1.y,q1.z,q1.w,
                    q2.x,q2.y,q2.z,q2.w, q3.x,q3.y,q3.z,q3.w};

    const ulonglong2* Wf2 = reinterpret_cast<const ulonglong2*>(c_pack);
    const ulonglong2* Ws2 = reinterpret_cast<const ulonglong2*>(c_pack + 256);
    const unsigned long long* bf2 = reinterpret_cast<const unsigned long long*>(c_pack + 384);
    const unsigned long long* bs2 = reinterpret_cast<const unsigned long long*>(c_pack + 400);

    unsigned long long f2[8], sd2[4];
    #pragma unroll
    for (int j = 0; j < 8; ++j) f2[j] = bf2[j];
    #pragma unroll
    for (int j = 0; j < 4; ++j) sd2[j] = bs2[j];

    #pragma unroll
    for (int k = 0; k < 16; ++k) {
        unsigned long long xp;
        PACK2_SAME(xp, xv[k]);
        const ulonglong2 w0 = Wf2[k*4+0], w1 = Wf2[k*4+1];
        const ulonglong2 w2 = Wf2[k*4+2], w3 = Wf2[k*4+3];
        FMA_F32X2(f2[0], xp, w0.x, f2[0]);
        FMA_F32X2(f2[1], xp, w0.y, f2[1]);
        FMA_F32X2(f2[2], xp, w1.x, f2[2]);
        FMA_F32X2(f2[3], xp, w1.y, f2[3]);
        FMA_F32X2(f2[4], xp, w2.x, f2[4]);
        FMA_F32X2(f2[5], xp, w2.y, f2[5]);
        FMA_F32X2(f2[6], xp, w3.x, f2[6]);
        FMA_F32X2(f2[7], xp, w3.y, f2[7]);
        const ulonglong2 u0 = Ws2[k*2+0], u1 = Ws2[k*2+1];
        FMA_F32X2(sd2[0], xp, u0.x, sd2[0]);
        FMA_F32X2(sd2[1], xp, u0.y, sd2[1]);
        FMA_F32X2(sd2[2], xp, u1.x, sd2[2]);
        FMA_F32X2(sd2[3], xp, u1.y, sd2[3]);
    }

    const bool m = (v < nv);
    float ew[8];
    #pragma unroll
    for (int j = 0; j < 4; ++j) {
        unsigned int lo, hi;
        UNPACK2(lo, hi, sd2[j]);
        ew[2*j]   = m ? exp2f(-__uint_as_float(lo)) : 0.0f;
        ew[2*j+1] = m ? exp2f(-__uint_as_float(hi)) : 0.0f;
    }

    // ew tile stays in shared memory — used again in phase 2
    ewt[t * 2]     = make_float4(ew[0], ew[1], ew[2], ew[3]);
    ewt[t * 2 + 1] = make_float4(ew[4], ew[5], ew[6], ew[7]);

    // stage pair-rows for reduction
    #pragma unroll
    for (int j = 0; j < 4; ++j) {
        unsigned long long ep;
        PACK2(ep, ew[2*j], ew[2*j+1]);
        red2[j * RS + t] = ep;
    }
    #pragma unroll
    for (int j = 0; j < 8; ++j)
        red2[(4 + j) * RS + t] = f2[j];
    __syncthreads();

    // quad reduction: thread t -> quad q (a-pair, p-pair), v-split vs
    {
        const int q  = t >> 2;
        const int vs = t & 3;
        const int apair = q >> 3;
        const int ppair = q & 7;
        const unsigned long long* er = &red2[apair * RS];
        const unsigned long long* fr = &red2[(4 + ppair) * RS];

        unsigned long long acc0 = 0ull, acc1 = 0ull;
        #pragma unroll
        for (int i = 0; i < 16; ++i) {
            const int col = vs * 2 + i * 8;
            const ulonglong2 e2  = *reinterpret_cast<const ulonglong2*>(er + col);
            const ulonglong2 ff2 = *reinterpret_cast<const ulonglong2*>(fr + col);
            unsigned int lo, hi;
            unsigned long long d0, d1;
            UNPACK2(lo, hi, e2.x);
            PACK2_SAME(d0, __uint_as_float(lo));
            PACK2_SAME(d1, __uint_as_float(hi));
            FMA_F32X2(acc0, d0, ff2.x, acc0);
            FMA_F32X2(acc1, d1, ff2.x, acc1);
            UNPACK2(lo, hi, e2.y);
            PACK2_SAME(d0, __uint_as_float(lo));
            PACK2_SAME(d1, __uint_as_float(hi));
            FMA_F32X2(acc0, d0, ff2.y, acc0);
            FMA_F32X2(acc1, d1, ff2.y, acc1);
        }
        comb[q * 8 + vs * 2 + 0] = acc0;
        comb[q * 8 + vs * 2 + 1] = acc1;
    }
    __syncthreads();

    // final combine -> g_part
    {
        const int a = t >> 4, p = t & 15;
        const int qq = (a >> 1) * 8 + (p >> 1);
        const float* cf = reinterpret_cast<const float*>(comb);
        float ssum = 0.f;
        #pragma unroll
        for (int vs = 0; vs < 4; ++vs)
            ssum += cf[(qq * 8 + vs * 2 + (a & 1)) * 2 + (p & 1)];
        g_part[((size_t)b * K1S + s) * 128 + t] = ssum;
    }

    // ---------------- arrival + tail M computation ----------------
    __threadfence();
    if (t == 0) {
        unsigned int r = atomicAdd(&g_cnt[b], 1u);
        s_tail = (r == K1S - 1) ? 1 : 0;
    }
    __syncthreads();

    if (s_tail) {
        // last block of batch b: partials -> agg -> M (comb area reused as agg)
        float acc = 0.f;
        #pragma unroll
        for (int sp = 0; sp < K1S; ++sp)
            acc += g_part[((size_t)b * K1S + sp) * 128 + t];
        agg_sh[t] = acc * (1.0f / (float)NV);
        __syncthreads();

        #pragma unroll
        for (int e = t; e < 256; e += 128) {
            const int a = e >> 5, n = e & 31;
            float mm = 0.f;
            #pragma unroll
            for (int p = 0; p < 16; ++p)
                mm += agg_sh[a * 16 + p] * W_out[(a * 16 + p) * 32 + n];
            g_M[b * 256 + e] = mm;
        }
        __threadfence();
        __syncthreads();
        if (t == 0)
            asm volatile("st.release.gpu.global.s32 [%0], %1;"
                         :: "l"(&g_flag[b]), "r"(1) : "memory");
    }

    // ---------------- spin-acquire M ready ----------------
    if (t == 0) {
        int f;
        while (true) {
            asm volatile("ld.acquire.gpu.global.s32 %0, [%1];"
                         : "=r"(f) : "l"(&g_flag[b]) : "memory");
            if (f) break;
            __nanosleep(64);
        }
    }
    __syncthreads();

    // ---------------- phase 2: epilogue ----------------
    const int ng = t & 7;
    const int vl = t >> 3;

    float4 Mr[8];
    {
        const float4* M4 = reinterpret_cast<const float4*>(g_M + b * 256);
        #pragma unroll
        for (int a = 0; a < 8; ++a) Mr[a] = M4[a * 8 + ng];
    }
    const float4 bo = reinterpret_cast<const float4*>(b_out)[ng];
    const float4 z = make_float4(0.f, 0.f, 0.f, 0.f);

    #pragma unroll
    for (int k = 0; k < 8; ++k) {
        const int vv = vl + k * 16;
        const float4 e0 = ewt[vv * 2];
        const float4 e1 = ewt[vv * 2 + 1];

        float4 acc = bo;
        acc.x += e0.x*Mr[0].x; acc.y += e0.x*Mr[0].y; acc.z += e0.x*Mr[0].z; acc.w += e0.x*Mr[0].w;
        acc.x += e0.y*Mr[1].x; acc.y += e0.y*Mr[1].y; acc.z += e0.y*Mr[1].z; acc.w += e0.y*Mr[1].w;
        acc.x += e0.z*Mr[2].x; acc.y += e0.z*Mr[2].y; acc.z += e0.z*Mr[2].z; acc.w += e0.z*Mr[2].w;
        acc.x += e0.w*Mr[3].x; acc.y += e0.w*Mr[3].y; acc.z += e0.w*Mr[3].z; acc.w += e0.w*Mr[3].w;
        acc.x += e1.x*Mr[4].x; acc.y += e1.x*Mr[4].y; acc.z += e1.x*Mr[4].z; acc.w += e1.x*Mr[4].w;
        acc.x += e1.y*Mr[5].x; acc.y += e1.y*Mr[5].y; acc.z += e1.y*Mr[5].z; acc.w += e1.y*Mr[5].w;
        acc.x += e1.z*Mr[6].x; acc.y += e1.z*Mr[6].y; acc.z += e1.z*Mr[6].z; acc.w += e1.z*Mr[6].w;
        acc.x += e1.w*Mr[7].x; acc.y += e1.w*Mr[7].y; acc.z += e1.w*Mr[7].z; acc.w += e1.w*Mr[7].w;

        otile[t + k * 128] = (s * K1V + vv < nv) ? acc : z;   // overwrites red2 (done)
    }
    __syncthreads();

    if (t == 0) {
        FENCE_ASYNC();
        unsigned int saddr = (unsigned int)__cvta_generic_to_shared(otile);
        float* gdst = out + ((size_t)b * NV + s * K1V) * NOUT;
        BULK_S2G(gdst, saddr, K1V * NOUT * 4);
        BULK_COMMIT();
        BULK_WAIT0();

        // bookkeeping reset for graph replay (last phase-2 finisher per batch)
        unsigned int d = atomicAdd(&g_done[b], 1u);
        if (d == K1S - 1) {
            g_cnt[b]  = 0;
            g_done[b] = 0;
            g_flag[b] = 0;
        }
    }
}

extern "C" void kernel_launch(void* const* d_in, const int* in_sizes, int n_in,
                              void* d_out, int out_size)
{
    const float* data       = (const float*)d_in[0];
    const int*   num_vertex = (const int*)  d_in[1];
    const float* W_flr      = (const float*)d_in[2];
    const float* b_flr      = (const float*)d_in[3];
    const float* W_s        = (const float*)d_in[4];
    const float* b_s        = (const float*)d_in[5];
    const float* W_out      = (const float*)d_in[6];
    const float* b_out      = (const float*)d_in[7];
    float*       out        = (float*)d_out;

    (void)in_sizes; (void)n_in; (void)out_size;

    garnet_kp<<<1, 128>>>(W_flr, W_s, b_flr, b_s);

    void* wpack_addr = nullptr;
    cudaGetSymbolAddress(&wpack_addr, g_wpack);
    cudaMemcpyToSymbolAsync(c_pack, wpack_addr, 408 * sizeof(float), 0,
                            cudaMemcpyDeviceToDevice);

    dim3 grid(K1S, NB);
    garnet_fused<<<grid, 128>>>(data, num_vertex, W_out, b_out, out);
}

// round 10
// speedup vs baseline: 1.2397x; 1.2397x over previous
#include <cuda_runtime.h>

// GarNet: B=256, V=1024, F=16, P=16, A=8, NF=32
// out[b,v,n] = mask(v) * ( sum_a ew[v,a] * M[b,a,n] + b_out[n] )
//   ew[v,a]  = mask(v) * 2^(-(data[v]·W_s + b_s)[a])
//   agg[a,p] = (1/V) sum_v ew[v,a] * (data[v]·W_flr + b_flr)[p]
//   M[a,n]   = sum_p agg[a,p] * W_out[a*P+p, n]
//
// Kp+copy:          pack small weights -> ONE copy -> __constant__.
// K1 (4x256 x128t): 2 v/thread feat+ew (f32x2, constant port), ew tile -> TMA
//                   bulk store overlapped with quad-product block reduction.
// Km (256 x128t):   partials -> agg -> M.
// K2 (8x256 x128t): f32x2 epilogue, out tile -> TMA bulk store.

#define NB   256
#define NV   1024
#define NFEA 16
#define NP   16
#define NA   8
#define NOUT 32

#define K1S  4
#define K1V  256
#define K2S  8
#define K2V  128

#define RS   258      // ull stride per pair-row (256 + 2)

__device__ float g_ew[NB * NV * NA];          // 8 MB
__device__ float g_part[NB * K1S * 128];      // 512 KB
__device__ float g_M[NB * NA * NOUT];         // 256 KB
__device__ float g_wpack[408];

// packed weights: [0,256) W_flr, [256,384) W_s, [384,400) b_flr, [400,408) b_s
__constant__ __align__(16) float c_pack[408];

#define FMA_F32X2(d, a, b, c) \
    asm("fma.rn.f32x2 %0, %1, %2, %3;" : "=l"(d) : "l"(a), "l"(b), "l"(c))
#define PACK2_SAME(out, x) \
    asm("mov.b64 %0, {%1, %1};" : "=l"(out) : "r"(__float_as_uint(x)))
#define PACK2(out, lo, hi) \
    asm("mov.b64 %0, {%1, %2};" : "=l"(out) : "r"(__float_as_uint(lo)), "r"(__float_as_uint(hi)))
#define UNPACK2(lo, hi, in) \
    asm("mov.b64 {%0, %1}, %2;" : "=r"(lo), "=r"(hi) : "l"(in))

#define BULK_S2G(gptr, saddr, bytes) \
    asm volatile("cp.async.bulk.global.shared::cta.bulk_group [%0], [%1], %2;" \
                 :: "l"(gptr), "r"(saddr), "r"(bytes) : "memory")
#define BULK_COMMIT() \
    asm volatile("cp.async.bulk.commit_group;" ::: "memory")
#define BULK_WAIT0() \
    asm volatile("cp.async.bulk.wait_group 0;" ::: "memory")
#define FENCE_ASYNC() \
    asm volatile("fence.proxy.async.shared::cta;" ::: "memory")

// ==================== Kp: pack weights into staging ====================
__global__ void __launch_bounds__(128)
garnet_kp(const float* __restrict__ W_flr,
          const float* __restrict__ W_s,
          const float* __restrict__ b_flr,
          const float* __restrict__ b_s)
{
    const int t = threadIdx.x;
    g_wpack[t]       = W_flr[t];
    g_wpack[t + 128] = W_flr[t + 128];
    g_wpack[t + 256] = W_s[t];
    if (t < 16) g_wpack[384 + t] = b_flr[t];
    if (t < 8)  g_wpack[400 + t] = b_s[t];
}

// ==================== K1 ====================
__global__ void __launch_bounds__(128, 5)
garnet_k1(const float* __restrict__ data,
          const int*   __restrict__ num_vertex)
{
    __shared__ __align__(16) unsigned long long red2[12 * RS];
    __shared__ __align__(16) unsigned long long comb[32 * 8];
    __shared__ __align__(16) float4 ewt[K1V * 2];     // 8KB ew tile

    const int t = threadIdx.x;
    const int s = blockIdx.x;      // 0..3
    const int b = blockIdx.y;
    const int v0 = s * K1V + t;
    const int v1 = v0 + 128;

    const float4* d40 = reinterpret_cast<const float4*>(data) + ((size_t)b * NV + v0) * 4;
    const float4* d41 = reinterpret_cast<const float4*>(data) + ((size_t)b * NV + v1) * 4;

    const ulonglong2* Wf2 = reinterpret_cast<const ulonglong2*>(c_pack);
    const ulonglong2* Ws2 = reinterpret_cast<const ulonglong2*>(c_pack + 256);
    const unsigned long long* bf2 = reinterpret_cast<const unsigned long long*>(c_pack + 384);
    const unsigned long long* bs2 = reinterpret_cast<const unsigned long long*>(c_pack + 400);

    unsigned long long f2a[8], f2b[8], sd2a[4], sd2b[4];
    #pragma unroll
    for (int j = 0; j < 8; ++j) { f2a[j] = bf2[j]; f2b[j] = bf2[j]; }
    #pragma unroll
    for (int j = 0; j < 4; ++j) { sd2a[j] = bs2[j]; sd2b[j] = bs2[j]; }

    const int nv = num_vertex[b];

    // two k-chunks of 8 to limit live registers
    #pragma unroll
    for (int c = 0; c < 2; ++c) {
        float4 qa0 = d40[c*2+0], qa1 = d40[c*2+1];
        float4 qb0 = d41[c*2+0], qb1 = d41[c*2+1];
        float xa[8] = {qa0.x,qa0.y,qa0.z,qa0.w, qa1.x,qa1.y,qa1.z,qa1.w};
        float xb[8] = {qb0.x,qb0.y,qb0.z,qb0.w, qb1.x,qb1.y,qb1.z,qb1.w};

        #pragma unroll
        for (int kk = 0; kk < 8; ++kk) {
            const int k = c * 8 + kk;
            unsigned long long xpa, xpb;
            PACK2_SAME(xpa, xa[kk]);
            PACK2_SAME(xpb, xb[kk]);
            const ulonglong2 w0 = Wf2[k*4+0], w1 = Wf2[k*4+1];
            const ulonglong2 w2 = Wf2[k*4+2], w3 = Wf2[k*4+3];
            FMA_F32X2(f2a[0], xpa, w0.x, f2a[0]);  FMA_F32X2(f2b[0], xpb, w0.x, f2b[0]);
            FMA_F32X2(f2a[1], xpa, w0.y, f2a[1]);  FMA_F32X2(f2b[1], xpb, w0.y, f2b[1]);
            FMA_F32X2(f2a[2], xpa, w1.x, f2a[2]);  FMA_F32X2(f2b[2], xpb, w1.x, f2b[2]);
            FMA_F32X2(f2a[3], xpa, w1.y, f2a[3]);  FMA_F32X2(f2b[3], xpb, w1.y, f2b[3]);
            FMA_F32X2(f2a[4], xpa, w2.x, f2a[4]);  FMA_F32X2(f2b[4], xpb, w2.x, f2b[4]);
            FMA_F32X2(f2a[5], xpa, w2.y, f2a[5]);  FMA_F32X2(f2b[5], xpb, w2.y, f2b[5]);
            FMA_F32X2(f2a[6], xpa, w3.x, f2a[6]);  FMA_F32X2(f2b[6], xpb, w3.x, f2b[6]);
            FMA_F32X2(f2a[7], xpa, w3.y, f2a[7]);  FMA_F32X2(f2b[7], xpb, w3.y, f2b[7]);
            const ulonglong2 u0 = Ws2[k*2+0], u1 = Ws2[k*2+1];
            FMA_F32X2(sd2a[0], xpa, u0.x, sd2a[0]);  FMA_F32X2(sd2b[0], xpb, u0.x, sd2b[0]);
            FMA_F32X2(sd2a[1], xpa, u0.y, sd2a[1]);  FMA_F32X2(sd2b[1], xpb, u0.y, sd2b[1]);
            FMA_F32X2(sd2a[2], xpa, u1.x, sd2a[2]);  FMA_F32X2(sd2b[2], xpb, u1.x, sd2b[2]);
            FMA_F32X2(sd2a[3], xpa, u1.y, sd2a[3]);  FMA_F32X2(sd2b[3], xpb, u1.y, sd2b[3]);
        }
    }

    // ew = mask * 2^(-dist); stage to smem tile + reduction rows
    {
        const bool ma = (v0 < nv), mb = (v1 < nv);
        float ewa[8], ewb[8];
        #pragma unroll
        for (int j = 0; j < 4; ++j) {
            unsigned int lo, hi;
            UNPACK2(lo, hi, sd2a[j]);
            ewa[2*j]   = ma ? exp2f(-__uint_as_float(lo)) : 0.0f;
            ewa[2*j+1] = ma ? exp2f(-__uint_as_float(hi)) : 0.0f;
            UNPACK2(lo, hi, sd2b[j]);
            ewb[2*j]   = mb ? exp2f(-__uint_as_float(lo)) : 0.0f;
            ewb[2*j+1] = mb ? exp2f(-__uint_as_float(hi)) : 0.0f;
        }

        ewt[t * 2]           = make_float4(ewa[0], ewa[1], ewa[2], ewa[3]);
        ewt[t * 2 + 1]       = make_float4(ewa[4], ewa[5], ewa[6], ewa[7]);
        ewt[(t + 128) * 2]     = make_float4(ewb[0], ewb[1], ewb[2], ewb[3]);
        ewt[(t + 128) * 2 + 1] = make_float4(ewb[4], ewb[5], ewb[6], ewb[7]);

        #pragma unroll
        for (int j = 0; j < 4; ++j) {
            unsigned long long ea, eb;
            PACK2(ea, ewa[2*j], ewa[2*j+1]);
            PACK2(eb, ewb[2*j], ewb[2*j+1]);
            red2[j * RS + t]       = ea;
            red2[j * RS + t + 128] = eb;
        }
        #pragma unroll
        for (int j = 0; j < 8; ++j) {
            red2[(4 + j) * RS + t]       = f2a[j];
            red2[(4 + j) * RS + t + 128] = f2b[j];
        }
    }
    __syncthreads();

    // TMA bulk store of ew tile — overlaps the reduction below
    if (t == 0) {
        FENCE_ASYNC();
        unsigned int saddr = (unsigned int)__cvta_generic_to_shared(ewt);
        float* gdst = g_ew + ((size_t)b * NV + s * K1V) * NA;
        BULK_S2G(gdst, saddr, K1V * NA * 4);
        BULK_COMMIT();
    }

    // quad reduction: thread t -> quad q (a-pair, p-pair), v-split vs
    {
        const int q  = t >> 2;
        const int vs = t & 3;
        const int apair = q >> 3;
        const int ppair = q & 7;
        const unsigned long long* er = &red2[apair * RS];
        const unsigned long long* fr = &red2[(4 + ppair) * RS];

        unsigned long long acc0 = 0ull, acc1 = 0ull;
        #pragma unroll
        for (int i = 0; i < 32; ++i) {
            const int col = vs * 2 + i * 8;
            const ulonglong2 e2  = *reinterpret_cast<const ulonglong2*>(er + col);
            const ulonglong2 ff2 = *reinterpret_cast<const ulonglong2*>(fr + col);
            unsigned int lo, hi;
            unsigned long long d0, d1;
            UNPACK2(lo, hi, e2.x);
            PACK2_SAME(d0, __uint_as_float(lo));
            PACK2_SAME(d1, __uint_as_float(hi));
            FMA_F32X2(acc0, d0, ff2.x, acc0);
            FMA_F32X2(acc1, d1, ff2.x, acc1);
            UNPACK2(lo, hi, e2.y);
            PACK2_SAME(d0, __uint_as_float(lo));
            PACK2_SAME(d1, __uint_as_float(hi));
            FMA_F32X2(acc0, d0, ff2.y, acc0);
            FMA_F32X2(acc1, d1, ff2.y, acc1);
        }
        comb[q * 8 + vs * 2 + 0] = acc0;
        comb[q * 8 + vs * 2 + 1] = acc1;
    }
    __syncthreads();

    // final combine: thread t -> (a = t>>4, p = t&15)
    {
        const int a = t >> 4, p = t & 15;
        const int qq = (a >> 1) * 8 + (p >> 1);
        const float* cf = reinterpret_cast<const float*>(comb);
        float ssum = 0.f;
        #pragma unroll
        for (int vs = 0; vs < 4; ++vs)
            ssum += cf[(qq * 8 + vs * 2 + (a & 1)) * 2 + (p & 1)];
        g_part[((size_t)b * K1S + s) * 128 + t] = ssum;
    }

    if (t == 0) BULK_WAIT0();
}

// ==================== Km ====================
__global__ void __launch_bounds__(128)
garnet_km(const float* __restrict__ W_out)
{
    __shared__ float agg_sh[128];
    __shared__ float Wo_sh[NA * NP * NOUT];

    const int t = threadIdx.x;
    const int b = blockIdx.x;

    {
        const float4* src = reinterpret_cast<const float4*>(W_out);
        float4* dst = reinterpret_cast<float4*>(Wo_sh);
        #pragma unroll
        for (int i = 0; i < 8; ++i) dst[t + i * 128] = src[t + i * 128];
    }

    float acc = 0.f;
    #pragma unroll
    for (int sp = 0; sp < K1S; ++sp)
        acc += g_part[((size_t)b * K1S + sp) * 128 + t];
    agg_sh[t] = acc * (1.0f / (float)NV);
    __syncthreads();

    #pragma unroll
    for (int e = t; e < 256; e += 128) {
        const int a = e >> 5, n = e & 31;
        float mm = 0.f;
        #pragma unroll
        for (int p = 0; p < 16; ++p)
            mm += agg_sh[a * 16 + p] * Wo_sh[(a * 16 + p) * 32 + n];
        g_M[b * 256 + e] = mm;
    }
}

// ==================== K2 ====================
__global__ void __launch_bounds__(128)
garnet_k2(const int*   __restrict__ num_vertex,
          const float* __restrict__ b_out,
          float*       __restrict__ out)
{
    __shared__ __align__(16) ulonglong2 tile2[K2V * NOUT / 4];  // 16KB out tile
    __shared__ float4 ew4_sh[K2V * 2];
    __shared__ float4 M4_sh[64];

    const int t  = threadIdx.x;
    const int s  = blockIdx.x;
    const int b  = blockIdx.y;
    const int ng = t & 7;
    const int vl = t >> 3;

    {
        const float4* src = reinterpret_cast<const float4*>(g_ew)
                          + ((size_t)b * NV + s * K2V) * 2;
        ew4_sh[t]       = src[t];
        ew4_sh[t + 128] = src[t + 128];
        if (t < 64)
            M4_sh[t] = reinterpret_cast<const float4*>(g_M + b * 256)[t];
    }
    const int nv = num_vertex[b];
    const float4 bo = reinterpret_cast<const float4*>(b_out)[ng];
    unsigned long long bo2lo, bo2hi;
    PACK2(bo2lo, bo.x, bo.y);
    PACK2(bo2hi, bo.z, bo.w);
    __syncthreads();

    // M column as packed n-pairs: Mr2[a] = {(M[a][4ng],M[a][4ng+1]), (M[a][4ng+2],M[a][4ng+3])}
    ulonglong2 Mr2[8];
    {
        const ulonglong2* M2 = reinterpret_cast<const ulonglong2*>(M4_sh);
        #pragma unroll
        for (int a = 0; a < 8; ++a) Mr2[a] = M2[a * 8 + ng];
    }

    const ulonglong2 z2 = make_ulonglong2(0ull, 0ull);

    #pragma unroll
    for (int k = 0; k < 8; ++k) {
        const int v = vl + k * 16;
        const float4 e0 = ew4_sh[v * 2];
        const float4 e1 = ew4_sh[v * 2 + 1];
        const float ew[8] = {e0.x, e0.y, e0.z, e0.w, e1.x, e1.y, e1.z, e1.w};

        unsigned long long acc0 = bo2lo, acc1 = bo2hi;
        #pragma unroll
        for (int a = 0; a < 8; ++a) {
            unsigned long long ep;
            PACK2_SAME(ep, ew[a]);
            FMA_F32X2(acc0, ep, Mr2[a].x, acc0);
            FMA_F32X2(acc1, ep, Mr2[a].y, acc1);
        }

        tile2[t + k * 128] = (s * K2V + v < nv) ? make_ulonglong2(acc0, acc1) : z2;
    }
    __syncthreads();

    if (t == 0) {
        FENCE_ASYNC();
        unsigned int saddr = (unsigned int)__cvta_generic_to_shared(tile2);
        float* gdst = out + ((size_t)b * NV + s * K2V) * NOUT;
        BULK_S2G(gdst, saddr, K2V * NOUT * 4);
        BULK_COMMIT();
        BULK_WAIT0();
    }
}

extern "C" void kernel_launch(void* const* d_in, const int* in_sizes, int n_in,
                              void* d_out, int out_size)
{
    const float* data       = (const float*)d_in[0];
    const int*   num_vertex = (const int*)  d_in[1];
    const float* W_flr      = (const float*)d_in[2];
    const float* b_flr      = (const float*)d_in[3];
    const float* W_s        = (const float*)d_in[4];
    const float* b_s        = (const float*)d_in[5];
    const float* W_out      = (const float*)d_in[6];
    const float* b_out      = (const float*)d_in[7];
    float*       out        = (float*)d_out;

    (void)in_sizes; (void)n_in; (void)out_size;

    garnet_kp<<<1, 128>>>(W_flr, W_s, b_flr, b_s);

    void* wpack_addr = nullptr;
    cudaGetSymbolAddress(&wpack_addr, g_wpack);
    cudaMemcpyToSymbolAsync(c_pack, wpack_addr, 408 * sizeof(float), 0,
                            cudaMemcpyDeviceToDevice);

    dim3 g1(K1S, NB), g2(K2S, NB);
    garnet_k1<<<g1, 128>>>(data, num_vertex);
    garnet_km<<<NB, 128>>>(W_out);
    garnet_k2<<<g2, 128>>>(num_vertex, b_out, out);
}

// round 11
// speedup vs baseline: 1.3006x; 1.0491x over previous
#include <cuda_runtime.h>

// GarNet: B=256, V=1024, F=16, P=16, A=8, NF=32
// out[b,v,n] = mask(v) * ( sum_a ew[v,a] * M[b,a,n] + b_out[n] )
//   ew[v,a]  = mask(v) * 2^(-(data[v]·W_s + b_s)[a])
//   agg[a,p] = (1/V) sum_v ew[v,a] * (data[v]·W_flr + b_flr)[p]
//   M[a,n]   = sum_p agg[a,p] * W_out[a*P+p, n]
//
// Kp+copy:          pack small weights -> ONE copy -> __constant__.
// K1 (4x256 x128t): 2 v/thread feat+ew (f32x2, constant port), ew tile -> TMA
//                   bulk store overlapped with quad-product block reduction.
// Km (256 x128t):   partials -> agg -> M.
// K2 (4x256 x256t): 256 vertices/block, f32x2 epilogue, M via direct LDG,
//                   single 32KB TMA bulk store.

#define NB   256
#define NV   1024
#define NFEA 16
#define NP   16
#define NA   8
#define NOUT 32

#define K1S  4
#define K1V  256
#define K2S  4
#define K2V  256

#define RS   258      // ull stride per pair-row (256 + 2)

__device__ float g_ew[NB * NV * NA];          // 8 MB
__device__ float g_part[NB * K1S * 128];      // 512 KB
__device__ float g_M[NB * NA * NOUT];         // 256 KB
__device__ float g_wpack[408];

// packed weights: [0,256) W_flr, [256,384) W_s, [384,400) b_flr, [400,408) b_s
__constant__ __align__(16) float c_pack[408];

#define FMA_F32X2(d, a, b, c) \
    asm("fma.rn.f32x2 %0, %1, %2, %3;" : "=l"(d) : "l"(a), "l"(b), "l"(c))
#define PACK2_SAME(out, x) \
    asm("mov.b64 %0, {%1, %1};" : "=l"(out) : "r"(__float_as_uint(x)))
#define PACK2(out, lo, hi) \
    asm("mov.b64 %0, {%1, %2};" : "=l"(out) : "r"(__float_as_uint(lo)), "r"(__float_as_uint(hi)))
#define UNPACK2(lo, hi, in) \
    asm("mov.b64 {%0, %1}, %2;" : "=r"(lo), "=r"(hi) : "l"(in))

#define BULK_S2G(gptr, saddr, bytes) \
    asm volatile("cp.async.bulk.global.shared::cta.bulk_group [%0], [%1], %2;" \
                 :: "l"(gptr), "r"(saddr), "r"(bytes) : "memory")
#define BULK_COMMIT() \
    asm volatile("cp.async.bulk.commit_group;" ::: "memory")
#define BULK_WAIT0() \
    asm volatile("cp.async.bulk.wait_group 0;" ::: "memory")
#define FENCE_ASYNC() \
    asm volatile("fence.proxy.async.shared::cta;" ::: "memory")

// ==================== Kp: pack weights into staging ====================
__global__ void __launch_bounds__(128)
garnet_kp(const float* __restrict__ W_flr,
          const float* __restrict__ W_s,
          const float* __restrict__ b_flr,
          const float* __restrict__ b_s)
{
    const int t = threadIdx.x;
    g_wpack[t]       = W_flr[t];
    g_wpack[t + 128] = W_flr[t + 128];
    g_wpack[t + 256] = W_s[t];
    if (t < 16) g_wpack[384 + t] = b_flr[t];
    if (t < 8)  g_wpack[400 + t] = b_s[t];
}

// ==================== K1 ====================
__global__ void __launch_bounds__(128, 5)
garnet_k1(const float* __restrict__ data,
          const int*   __restrict__ num_vertex)
{
    __shared__ __align__(16) unsigned long long red2[12 * RS];
    __shared__ __align__(16) unsigned long long comb[32 * 8];
    __shared__ __align__(16) float4 ewt[K1V * 2];     // 8KB ew tile

    const int t = threadIdx.x;
    const int s = blockIdx.x;      // 0..3
    const int b = blockIdx.y;
    const int v0 = s * K1V + t;
    const int v1 = v0 + 128;

    const float4* d40 = reinterpret_cast<const float4*>(data) + ((size_t)b * NV + v0) * 4;
    const float4* d41 = reinterpret_cast<const float4*>(data) + ((size_t)b * NV + v1) * 4;

    const ulonglong2* Wf2 = reinterpret_cast<const ulonglong2*>(c_pack);
    const ulonglong2* Ws2 = reinterpret_cast<const ulonglong2*>(c_pack + 256);
    const unsigned long long* bf2 = reinterpret_cast<const unsigned long long*>(c_pack + 384);
    const unsigned long long* bs2 = reinterpret_cast<const unsigned long long*>(c_pack + 400);

    unsigned long long f2a[8], f2b[8], sd2a[4], sd2b[4];
    #pragma unroll
    for (int j = 0; j < 8; ++j) { f2a[j] = bf2[j]; f2b[j] = bf2[j]; }
    #pragma unroll
    for (int j = 0; j < 4; ++j) { sd2a[j] = bs2[j]; sd2b[j] = bs2[j]; }

    const int nv = num_vertex[b];

    #pragma unroll
    for (int c = 0; c < 2; ++c) {
        float4 qa0 = d40[c*2+0], qa1 = d40[c*2+1];
        float4 qb0 = d41[c*2+0], qb1 = d41[c*2+1];
        float xa[8] = {qa0.x,qa0.y,qa0.z,qa0.w, qa1.x,qa1.y,qa1.z,qa1.w};
        float xb[8] = {qb0.x,qb0.y,qb0.z,qb0.w, qb1.x,qb1.y,qb1.z,qb1.w};

        #pragma unroll
        for (int kk = 0; kk < 8; ++kk) {
            const int k = c * 8 + kk;
            unsigned long long xpa, xpb;
            PACK2_SAME(xpa, xa[kk]);
            PACK2_SAME(xpb, xb[kk]);
            const ulonglong2 w0 = Wf2[k*4+0], w1 = Wf2[k*4+1];
            const ulonglong2 w2 = Wf2[k*4+2], w3 = Wf2[k*4+3];
            FMA_F32X2(f2a[0], xpa, w0.x, f2a[0]);  FMA_F32X2(f2b[0], xpb, w0.x, f2b[0]);
            FMA_F32X2(f2a[1], xpa, w0.y, f2a[1]);  FMA_F32X2(f2b[1], xpb, w0.y, f2b[1]);
            FMA_F32X2(f2a[2], xpa, w1.x, f2a[2]);  FMA_F32X2(f2b[2], xpb, w1.x, f2b[2]);
            FMA_F32X2(f2a[3], xpa, w1.y, f2a[3]);  FMA_F32X2(f2b[3], xpb, w1.y, f2b[3]);
            FMA_F32X2(f2a[4], xpa, w2.x, f2a[4]);  FMA_F32X2(f2b[4], xpb, w2.x, f2b[4]);
            FMA_F32X2(f2a[5], xpa, w2.y, f2a[5]);  FMA_F32X2(f2b[5], xpb, w2.y, f2b[5]);
            FMA_F32X2(f2a[6], xpa, w3.x, f2a[6]);  FMA_F32X2(f2b[6], xpb, w3.x, f2b[6]);
            FMA_F32X2(f2a[7], xpa, w3.y, f2a[7]);  FMA_F32X2(f2b[7], xpb, w3.y, f2b[7]);
            const ulonglong2 u0 = Ws2[k*2+0], u1 = Ws2[k*2+1];
            FMA_F32X2(sd2a[0], xpa, u0.x, sd2a[0]);  FMA_F32X2(sd2b[0], xpb, u0.x, sd2b[0]);
            FMA_F32X2(sd2a[1], xpa, u0.y, sd2a[1]);  FMA_F32X2(sd2b[1], xpb, u0.y, sd2b[1]);
            FMA_F32X2(sd2a[2], xpa, u1.x, sd2a[2]);  FMA_F32X2(sd2b[2], xpb, u1.x, sd2b[2]);
            FMA_F32X2(sd2a[3], xpa, u1.y, sd2a[3]);  FMA_F32X2(sd2b[3], xpb, u1.y, sd2b[3]);
        }
    }

    // ew = mask * 2^(-dist); stage to smem tile + reduction rows
    {
        const bool ma = (v0 < nv), mb = (v1 < nv);
        float ewa[8], ewb[8];
        #pragma unroll
        for (int j = 0; j < 4; ++j) {
            unsigned int lo, hi;
            UNPACK2(lo, hi, sd2a[j]);
            ewa[2*j]   = ma ? exp2f(-__uint_as_float(lo)) : 0.0f;
            ewa[2*j+1] = ma ? exp2f(-__uint_as_float(hi)) : 0.0f;
            UNPACK2(lo, hi, sd2b[j]);
            ewb[2*j]   = mb ? exp2f(-__uint_as_float(lo)) : 0.0f;
            ewb[2*j+1] = mb ? exp2f(-__uint_as_float(hi)) : 0.0f;
        }

        ewt[t * 2]             = make_float4(ewa[0], ewa[1], ewa[2], ewa[3]);
        ewt[t * 2 + 1]         = make_float4(ewa[4], ewa[5], ewa[6], ewa[7]);
        ewt[(t + 128) * 2]     = make_float4(ewb[0], ewb[1], ewb[2], ewb[3]);
        ewt[(t + 128) * 2 + 1] = make_float4(ewb[4], ewb[5], ewb[6], ewb[7]);

        #pragma unroll
        for (int j = 0; j < 4; ++j) {
            unsigned long long ea, eb;
            PACK2(ea, ewa[2*j], ewa[2*j+1]);
            PACK2(eb, ewb[2*j], ewb[2*j+1]);
            red2[j * RS + t]       = ea;
            red2[j * RS + t + 128] = eb;
        }
        #pragma unroll
        for (int j = 0; j < 8; ++j) {
            red2[(4 + j) * RS + t]       = f2a[j];
            red2[(4 + j) * RS + t + 128] = f2b[j];
        }
    }
    __syncthreads();

    // TMA bulk store of ew tile — overlaps the reduction below
    if (t == 0) {
        FENCE_ASYNC();
        unsigned int saddr = (unsigned int)__cvta_generic_to_shared(ewt);
        float* gdst = g_ew + ((size_t)b * NV + s * K1V) * NA;
        BULK_S2G(gdst, saddr, K1V * NA * 4);
        BULK_COMMIT();
    }

    // quad reduction
    {
        const int q  = t >> 2;
        const int vs = t & 3;
        const int apair = q >> 3;
        const int ppair = q & 7;
        const unsigned long long* er = &red2[apair * RS];
        const unsigned long long* fr = &red2[(4 + ppair) * RS];

        unsigned long long acc0 = 0ull, acc1 = 0ull;
        #pragma unroll
        for (int i = 0; i < 32; ++i) {
            const int col = vs * 2 + i * 8;
            const ulonglong2 e2  = *reinterpret_cast<const ulonglong2*>(er + col);
            const ulonglong2 ff2 = *reinterpret_cast<const ulonglong2*>(fr + col);
            unsigned int lo, hi;
            unsigned long long d0, d1;
            UNPACK2(lo, hi, e2.x);
            PACK2_SAME(d0, __uint_as_float(lo));
            PACK2_SAME(d1, __uint_as_float(hi));
            FMA_F32X2(acc0, d0, ff2.x, acc0);
            FMA_F32X2(acc1, d1, ff2.x, acc1);
            UNPACK2(lo, hi, e2.y);
            PACK2_SAME(d0, __uint_as_float(lo));
            PACK2_SAME(d1, __uint_as_float(hi));
            FMA_F32X2(acc0, d0, ff2.y, acc0);
            FMA_F32X2(acc1, d1, ff2.y, acc1);
        }
        comb[q * 8 + vs * 2 + 0] = acc0;
        comb[q * 8 + vs * 2 + 1] = acc1;
    }
    __syncthreads();

    {
        const int a = t >> 4, p = t & 15;
        const int qq = (a >> 1) * 8 + (p >> 1);
        const float* cf = reinterpret_cast<const float*>(comb);
        float ssum = 0.f;
        #pragma unroll
        for (int vs = 0; vs < 4; ++vs)
            ssum += cf[(qq * 8 + vs * 2 + (a & 1)) * 2 + (p & 1)];
        g_part[((size_t)b * K1S + s) * 128 + t] = ssum;
    }

    if (t == 0) BULK_WAIT0();
}

// ==================== Km ====================
__global__ void __launch_bounds__(128)
garnet_km(const float* __restrict__ W_out)
{
    __shared__ float agg_sh[128];
    __shared__ float Wo_sh[NA * NP * NOUT];

    const int t = threadIdx.x;
    const int b = blockIdx.x;

    {
        const float4* src = reinterpret_cast<const float4*>(W_out);
        float4* dst = reinterpret_cast<float4*>(Wo_sh);
        #pragma unroll
        for (int i = 0; i < 8; ++i) dst[t + i * 128] = src[t + i * 128];
    }

    float acc = 0.f;
    #pragma unroll
    for (int sp = 0; sp < K1S; ++sp)
        acc += g_part[((size_t)b * K1S + sp) * 128 + t];
    agg_sh[t] = acc * (1.0f / (float)NV);
    __syncthreads();

    #pragma unroll
    for (int e = t; e < 256; e += 128) {
        const int a = e >> 5, n = e & 31;
        float mm = 0.f;
        #pragma unroll
        for (int p = 0; p < 16; ++p)
            mm += agg_sh[a * 16 + p] * Wo_sh[(a * 16 + p) * 32 + n];
        g_M[b * 256 + e] = mm;
    }
}

// ==================== K2: 256 threads, 256 vertices/block ====================
__global__ void __launch_bounds__(256)
garnet_k2(const int*   __restrict__ num_vertex,
          const float* __restrict__ b_out,
          float*       __restrict__ out)
{
    __shared__ __align__(16) ulonglong2 tile2[K2V * NOUT / 4];  // 32KB out tile
    __shared__ float4 ew4_sh[K2V * 2];                          // 8KB

    const int t  = threadIdx.x;
    const int s  = blockIdx.x;      // 0..3
    const int b  = blockIdx.y;
    const int ng = t & 7;
    const int vl = t >> 3;          // 0..31

    // ew staging (2 LDG.128 + 2 STS.128 per thread)
    {
        const float4* src = reinterpret_cast<const float4*>(g_ew)
                          + ((size_t)b * NV + s * K2V) * 2;
        ew4_sh[t]       = src[t];
        ew4_sh[t + 256] = src[t + 256];
    }

    // M column direct from global (L2-hot), no smem staging
    ulonglong2 Mr2[8];
    {
        const ulonglong2* M2 = reinterpret_cast<const ulonglong2*>(g_M + b * 256);
        #pragma unroll
        for (int a = 0; a < 8; ++a) Mr2[a] = __ldg(M2 + a * 8 + ng);
    }
    const int nv = num_vertex[b];
    const float4 bo = reinterpret_cast<const float4*>(b_out)[ng];
    unsigned long long bo2lo, bo2hi;
    PACK2(bo2lo, bo.x, bo.y);
    PACK2(bo2hi, bo.z, bo.w);
    const ulonglong2 z2 = make_ulonglong2(0ull, 0ull);
    __syncthreads();

    #pragma unroll
    for (int k = 0; k < 8; ++k) {
        const int v = vl + k * 32;
        const float4 e0 = ew4_sh[v * 2];
        const float4 e1 = ew4_sh[v * 2 + 1];
        const float ew[8] = {e0.x, e0.y, e0.z, e0.w, e1.x, e1.y, e1.z, e1.w};

        unsigned long long acc0 = bo2lo, acc1 = bo2hi;
        #pragma unroll
        for (int a = 0; a < 8; ++a) {
            unsigned long long ep;
            PACK2_SAME(ep, ew[a]);
            FMA_F32X2(acc0, ep, Mr2[a].x, acc0);
            FMA_F32X2(acc1, ep, Mr2[a].y, acc1);
        }

        tile2[t + k * 256] = (s * K2V + v < nv) ? make_ulonglong2(acc0, acc1) : z2;
    }
    __syncthreads();

    if (t == 0) {
        FENCE_ASYNC();
        unsigned int saddr = (unsigned int)__cvta_generic_to_shared(tile2);
        float* gdst = out + ((size_t)b * NV + s * K2V) * NOUT;
        BULK_S2G(gdst, saddr, K2V * NOUT * 4);
        BULK_COMMIT();
        BULK_WAIT0();
    }
}

extern "C" void kernel_launch(void* const* d_in, const int* in_sizes, int n_in,
                              void* d_out, int out_size)
{
    const float* data       = (const float*)d_in[0];
    const int*   num_vertex = (const int*)  d_in[1];
    const float* W_flr      = (const float*)d_in[2];
    const float* b_flr      = (const float*)d_in[3];
    const float* W_s        = (const float*)d_in[4];
    const float* b_s        = (const float*)d_in[5];
    const float* W_out      = (const float*)d_in[6];
    const float* b_out      = (const float*)d_in[7];
    float*       out        = (float*)d_out;

    (void)in_sizes; (void)n_in; (void)out_size;

    garnet_kp<<<1, 128>>>(W_flr, W_s, b_flr, b_s);

    void* wpack_addr = nullptr;
    cudaGetSymbolAddress(&wpack_addr, g_wpack);
    cudaMemcpyToSymbolAsync(c_pack, wpack_addr, 408 * sizeof(float), 0,
                            cudaMemcpyDeviceToDevice);

    dim3 g1(K1S, NB), g2(K2S, NB);
    garnet_k1<<<g1, 128>>>(data, num_vertex);
    garnet_km<<<NB, 128>>>(W_out);
    garnet_k2<<<g2, 256>>>(num_vertex, b_out, out);
}

// round 13
// speedup vs baseline: 1.3021x; 1.0012x over previous
#include <cuda_runtime.h>

// GarNet: B=256, V=1024, F=16, P=16, A=8, NF=32
// out[b,v,n] = mask(v) * ( sum_a ew[v,a] * M[b,a,n] + b_out[n] )
//   ew[v,a]  = mask(v) * 2^(-(data[v]·W_s + b_s)[a])
//   agg[a,p] = (1/V) sum_v ew[v,a] * (data[v]·W_flr + b_flr)[p]
//   M[a,n]   = sum_p agg[a,p] * W_out[a*P+p, n]
//
// Kp+copy:          pack small weights -> ONE copy -> __constant__.
// K1 (4x256 x128t): 2 v/thread feat+ew (f32x2, constant port), ew tile -> TMA
//                   bulk store overlapped with quad-product block reduction.
// Km (256 x128t):   PDL — W_out staged pre-sync, then partials -> agg -> M.
// K2 (8x256 x128t): PDL — indep prologue pre-sync, f32x2 epilogue, TMA store.

#define NB   256
#define NV   1024
#define NFEA 16
#define NP   16
#define NA   8
#define NOUT 32

#define K1S  4
#define K1V  256
#define K2S  8
#define K2V  128

#define RS   258      // ull stride per pair-row (256 + 2)

__device__ float g_ew[NB * NV * NA];          // 8 MB
__device__ float g_part[NB * K1S * 128];      // 512 KB
__device__ float g_M[NB * NA * NOUT];         // 256 KB
__device__ float g_wpack[408];

// packed weights: [0,256) W_flr, [256,384) W_s, [384,400) b_flr, [400,408) b_s
__constant__ __align__(16) float c_pack[408];

#define FMA_F32X2(d, a, b, c) \
    asm("fma.rn.f32x2 %0, %1, %2, %3;" : "=l"(d) : "l"(a), "l"(b), "l"(c))
#define PACK2_SAME(out, x) \
    asm("mov.b64 %0, {%1, %1};" : "=l"(out) : "r"(__float_as_uint(x)))
#define PACK2(out, lo, hi) \
    asm("mov.b64 %0, {%1, %2};" : "=l"(out) : "r"(__float_as_uint(lo)), "r"(__float_as_uint(hi)))
#define UNPACK2(lo, hi, in) \
    asm("mov.b64 {%0, %1}, %2;" : "=r"(lo), "=r"(hi) : "l"(in))

#define BULK_S2G(gptr, saddr, bytes) \
    asm volatile("cp.async.bulk.global.shared::cta.bulk_group [%0], [%1], %2;" \
                 :: "l"(gptr), "r"(saddr), "r"(bytes) : "memory")
#define BULK_COMMIT() \
    asm volatile("cp.async.bulk.commit_group;" ::: "memory")
#define BULK_WAIT0() \
    asm volatile("cp.async.bulk.wait_group 0;" ::: "memory")
#define FENCE_ASYNC() \
    asm volatile("fence.proxy.async.shared::cta;" ::: "memory")

// ==================== Kp: pack weights into staging ====================
__global__ void __launch_bounds__(128)
garnet_kp(const float* __restrict__ W_flr,
          const float* __restrict__ W_s,
          const float* __restrict__ b_flr,
          const float* __restrict__ b_s)
{
    const int t = threadIdx.x;
    g_wpack[t]       = W_flr[t];
    g_wpack[t + 128] = W_flr[t + 128];
    g_wpack[t + 256] = W_s[t];
    if (t < 16) g_wpack[384 + t] = b_flr[t];
    if (t < 8)  g_wpack[400 + t] = b_s[t];
}

// ==================== K1 ====================
__global__ void __launch_bounds__(128, 5)
garnet_k1(const float* __restrict__ data,
          const int*   __restrict__ num_vertex)
{
    __shared__ __align__(16) unsigned long long red2[12 * RS];
    __shared__ __align__(16) unsigned long long comb[32 * 8];
    __shared__ __align__(16) float4 ewt[K1V * 2];     // 8KB ew tile

    const int t = threadIdx.x;
    const int s = blockIdx.x;      // 0..3
    const int b = blockIdx.y;
    const int v0 = s * K1V + t;
    const int v1 = v0 + 128;

    const float4* d40 = reinterpret_cast<const float4*>(data) + ((size_t)b * NV + v0) * 4;
    const float4* d41 = reinterpret_cast<const float4*>(data) + ((size_t)b * NV + v1) * 4;

    const ulonglong2* Wf2 = reinterpret_cast<const ulonglong2*>(c_pack);
    const ulonglong2* Ws2 = reinterpret_cast<const ulonglong2*>(c_pack + 256);
    const unsigned long long* bf2 = reinterpret_cast<const unsigned long long*>(c_pack + 384);
    const unsigned long long* bs2 = reinterpret_cast<const unsigned long long*>(c_pack + 400);

    unsigned long long f2a[8], f2b[8], sd2a[4], sd2b[4];
    #pragma unroll
    for (int j = 0; j < 8; ++j) { f2a[j] = bf2[j]; f2b[j] = bf2[j]; }
    #pragma unroll
    for (int j = 0; j < 4; ++j) { sd2a[j] = bs2[j]; sd2b[j] = bs2[j]; }

    const int nv = num_vertex[b];

    #pragma unroll
    for (int c = 0; c < 2; ++c) {
        float4 qa0 = d40[c*2+0], qa1 = d40[c*2+1];
        float4 qb0 = d41[c*2+0], qb1 = d41[c*2+1];
        float xa[8] = {qa0.x,qa0.y,qa0.z,qa0.w, qa1.x,qa1.y,qa1.z,qa1.w};
        float xb[8] = {qb0.x,qb0.y,qb0.z,qb0.w, qb1.x,qb1.y,qb1.z,qb1.w};

        #pragma unroll
        for (int kk = 0; kk < 8; ++kk) {
            const int k = c * 8 + kk;
            unsigned long long xpa, xpb;
            PACK2_SAME(xpa, xa[kk]);
            PACK2_SAME(xpb, xb[kk]);
            const ulonglong2 w0 = Wf2[k*4+0], w1 = Wf2[k*4+1];
            const ulonglong2 w2 = Wf2[k*4+2], w3 = Wf2[k*4+3];
            FMA_F32X2(f2a[0], xpa, w0.x, f2a[0]);  FMA_F32X2(f2b[0], xpb, w0.x, f2b[0]);
            FMA_F32X2(f2a[1], xpa, w0.y, f2a[1]);  FMA_F32X2(f2b[1], xpb, w0.y, f2b[1]);
            FMA_F32X2(f2a[2], xpa, w1.x, f2a[2]);  FMA_F32X2(f2b[2], xpb, w1.x, f2b[2]);
            FMA_F32X2(f2a[3], xpa, w1.y, f2a[3]);  FMA_F32X2(f2b[3], xpb, w1.y, f2b[3]);
            FMA_F32X2(f2a[4], xpa, w2.x, f2a[4]);  FMA_F32X2(f2b[4], xpb, w2.x, f2b[4]);
            FMA_F32X2(f2a[5], xpa, w2.y, f2a[5]);  FMA_F32X2(f2b[5], xpb, w2.y, f2b[5]);
            FMA_F32X2(f2a[6], xpa, w3.x, f2a[6]);  FMA_F32X2(f2b[6], xpb, w3.x, f2b[6]);
            FMA_F32X2(f2a[7], xpa, w3.y, f2a[7]);  FMA_F32X2(f2b[7], xpb, w3.y, f2b[7]);
            const ulonglong2 u0 = Ws2[k*2+0], u1 = Ws2[k*2+1];
            FMA_F32X2(sd2a[0], xpa, u0.x, sd2a[0]);  FMA_F32X2(sd2b[0], xpb, u0.x, sd2b[0]);
            FMA_F32X2(sd2a[1], xpa, u0.y, sd2a[1]);  FMA_F32X2(sd2b[1], xpb, u0.y, sd2b[1]);
            FMA_F32X2(sd2a[2], xpa, u1.x, sd2a[2]);  FMA_F32X2(sd2b[2], xpb, u1.x, sd2b[2]);
            FMA_F32X2(sd2a[3], xpa, u1.y, sd2a[3]);  FMA_F32X2(sd2b[3], xpb, u1.y, sd2b[3]);
        }
    }

    // ew = mask * 2^(-dist); stage to smem tile + reduction rows
    {
        const bool ma = (v0 < nv), mb = (v1 < nv);
        float ewa[8], ewb[8];
        #pragma unroll
        for (int j = 0; j < 4; ++j) {
            unsigned int lo, hi;
            UNPACK2(lo, hi, sd2a[j]);
            ewa[2*j]   = ma ? exp2f(-__uint_as_float(lo)) : 0.0f;
            ewa[2*j+1] = ma ? exp2f(-__uint_as_float(hi)) : 0.0f;
            UNPACK2(lo, hi, sd2b[j]);
            ewb[2*j]   = mb ? exp2f(-__uint_as_float(lo)) : 0.0f;
            ewb[2*j+1] = mb ? exp2f(-__uint_as_float(hi)) : 0.0f;
        }

        ewt[t * 2]             = make_float4(ewa[0], ewa[1], ewa[2], ewa[3]);
        ewt[t * 2 + 1]         = make_float4(ewa[4], ewa[5], ewa[6], ewa[7]);
        ewt[(t + 128) * 2]     = make_float4(ewb[0], ewb[1], ewb[2], ewb[3]);
        ewt[(t + 128) * 2 + 1] = make_float4(ewb[4], ewb[5], ewb[6], ewb[7]);

        #pragma unroll
        for (int j = 0; j < 4; ++j) {
            unsigned long long ea, eb;
            PACK2(ea, ewa[2*j], ewa[2*j+1]);
            PACK2(eb, ewb[2*j], ewb[2*j+1]);
            red2[j * RS + t]       = ea;
            red2[j * RS + t + 128] = eb;
        }
        #pragma unroll
        for (int j = 0; j < 8; ++j) {
            red2[(4 + j) * RS + t]       = f2a[j];
            red2[(4 + j) * RS + t + 128] = f2b[j];
        }
    }
    __syncthreads();

    // TMA bulk store of ew tile — overlaps the reduction below
    if (t == 0) {
        FENCE_ASYNC();
        unsigned int saddr = (unsigned int)__cvta_generic_to_shared(ewt);
        float* gdst = g_ew + ((size_t)b * NV + s * K1V) * NA;
        BULK_S2G(gdst, saddr, K1V * NA * 4);
        BULK_COMMIT();
    }

    // quad reduction
    {
        const int q  = t >> 2;
        const int vs = t & 3;
        const int apair = q >> 3;
        const int ppair = q & 7;
        const unsigned long long* er = &red2[apair * RS];
        const unsigned long long* fr = &red2[(4 + ppair) * RS];

        unsigned long long acc0 = 0ull, acc1 = 0ull;
        #pragma unroll
        for (int i = 0; i < 32; ++i) {
            const int col = vs * 2 + i * 8;
            const ulonglong2 e2  = *reinterpret_cast<const ulonglong2*>(er + col);
            const ulonglong2 ff2 = *reinterpret_cast<const ulonglong2*>(fr + col);
            unsigned int lo, hi;
            unsigned long long d0, d1;
            UNPACK2(lo, hi, e2.x);
            PACK2_SAME(d0, __uint_as_float(lo));
            PACK2_SAME(d1, __uint_as_float(hi));
            FMA_F32X2(acc0, d0, ff2.x, acc0);
            FMA_F32X2(acc1, d1, ff2.x, acc1);
            UNPACK2(lo, hi, e2.y);
            PACK2_SAME(d0, __uint_as_float(lo));
            PACK2_SAME(d1, __uint_as_float(hi));
            FMA_F32X2(acc0, d0, ff2.y, acc0);
            FMA_F32X2(acc1, d1, ff2.y, acc1);
        }
        comb[q * 8 + vs * 2 + 0] = acc0;
        comb[q * 8 + vs * 2 + 1] = acc1;
    }
    __syncthreads();

    {
        const int a = t >> 4, p = t & 15;
        const int qq = (a >> 1) * 8 + (p >> 1);
        const float* cf = reinterpret_cast<const float*>(comb);
        float ssum = 0.f;
        #pragma unroll
        for (int vs = 0; vs < 4; ++vs)
            ssum += cf[(qq * 8 + vs * 2 + (a & 1)) * 2 + (p & 1)];
        g_part[((size_t)b * K1S + s) * 128 + t] = ssum;
    }

    if (t == 0) BULK_WAIT0();
}

// ==================== Km (PDL: W_out staged before grid sync) ====================
__global__ void __launch_bounds__(128)
garnet_km(const float* __restrict__ W_out)
{
    __shared__ float agg_sh[128];
    __shared__ float Wo_sh[NA * NP * NOUT];

    const int t = threadIdx.x;
    const int b = blockIdx.x;

    // pre-sync: stage W_out (independent of K1) — overlaps K1 tail
    {
        const float4* src = reinterpret_cast<const float4*>(W_out);
        float4* dst = reinterpret_cast<float4*>(Wo_sh);
        #pragma unroll
        for (int i = 0; i < 8; ++i) dst[t + i * 128] = src[t + i * 128];
    }

    cudaGridDependencySynchronize();   // wait for K1's g_part writes

    float acc = 0.f;
    #pragma unroll
    for (int sp = 0; sp < K1S; ++sp)
        acc += g_part[((size_t)b * K1S + sp) * 128 + t];
    agg_sh[t] = acc * (1.0f / (float)NV);
    __syncthreads();

    #pragma unroll
    for (int e = t; e < 256; e += 128) {
        const int a = e >> 5, n = e & 31;
        float mm = 0.f;
        #pragma unroll
        for (int p = 0; p < 16; ++p)
            mm += agg_sh[a * 16 + p] * Wo_sh[(a * 16 + p) * 32 + n];
        g_M[b * 256 + e] = mm;
    }
}

// ==================== K2 (PDL: independent prologue before grid sync) ========
__global__ void __launch_bounds__(128)
garnet_k2(const int*   __restrict__ num_vertex,
          const float* __restrict__ b_out,
          float*       __restrict__ out)
{
    __shared__ __align__(16) ulonglong2 tile2[K2V * NOUT / 4];  // 16KB out tile
    __shared__ float4 ew4_sh[K2V * 2];
    __shared__ float4 M4_sh[64];

    const int t  = threadIdx.x;
    const int s  = blockIdx.x;
    const int b  = blockIdx.y;
    const int ng = t & 7;
    const int vl = t >> 3;

    // pre-sync: inputs independent of K1/Km
    const int nv = num_vertex[b];
    const float4 bo = reinterpret_cast<const float4*>(b_out)[ng];
    unsigned long long bo2lo, bo2hi;
    PACK2(bo2lo, bo.x, bo.y);
    PACK2(bo2hi, bo.z, bo.w);

    cudaGridDependencySynchronize();   // wait for Km (and transitively K1)

    {
        const float4* src = reinterpret_cast<const float4*>(g_ew)
                          + ((size_t)b * NV + s * K2V) * 2;
        ew4_sh[t]       = src[t];
        ew4_sh[t + 128] = src[t + 128];
        if (t < 64)
            M4_sh[t] = reinterpret_cast<const float4*>(g_M + b * 256)[t];
    }
    __syncthreads();

    ulonglong2 Mr2[8];
    {
        const ulonglong2* M2 = reinterpret_cast<const ulonglong2*>(M4_sh);
        #pragma unroll
        for (int a = 0; a < 8; ++a) Mr2[a] = M2[a * 8 + ng];
    }

    const ulonglong2 z2 = make_ulonglong2(0ull, 0ull);

    #pragma unroll
    for (int k = 0; k < 8; ++k) {
        const int v = vl + k * 16;
        const float4 e0 = ew4_sh[v * 2];
        const float4 e1 = ew4_sh[v * 2 + 1];
        const float ew[8] = {e0.x, e0.y, e0.z, e0.w, e1.x, e1.y, e1.z, e1.w};

        unsigned long long acc0 = bo2lo, acc1 = bo2hi;
        #pragma unroll
        for (int a = 0; a < 8; ++a) {
            unsigned long long ep;
            PACK2_SAME(ep, ew[a]);
            FMA_F32X2(acc0, ep, Mr2[a].x, acc0);
            FMA_F32X2(acc1, ep, Mr2[a].y, acc1);
        }

        tile2[t + k * 128] = (s * K2V + v < nv) ? make_ulonglong2(acc0, acc1) : z2;
    }
    __syncthreads();

    if (t == 0) {
        FENCE_ASYNC();
        unsigned int saddr = (unsigned int)__cvta_generic_to_shared(tile2);
        float* gdst = out + ((size_t)b * NV + s * K2V) * NOUT;
        BULK_S2G(gdst, saddr, K2V * NOUT * 4);
        BULK_COMMIT();
        BULK_WAIT0();
    }
}

extern "C" void kernel_launch(void* const* d_in, const int* in_sizes, int n_in,
                              void* d_out, int out_size)
{
    const float* data       = (const float*)d_in[0];
    const int*   num_vertex = (const int*)  d_in[1];
    const float* W_flr      = (const float*)d_in[2];
    const float* b_flr      = (const float*)d_in[3];
    const float* W_s        = (const float*)d_in[4];
    const float* b_s        = (const float*)d_in[5];
    const float* W_out      = (const float*)d_in[6];
    const float* b_out      = (const float*)d_in[7];
    float*       out        = (float*)d_out;

    (void)in_sizes; (void)n_in; (void)out_size;

    garnet_kp<<<1, 128>>>(W_flr, W_s, b_flr, b_s);

    void* wpack_addr = nullptr;
    cudaGetSymbolAddress(&wpack_addr, g_wpack);
    cudaMemcpyToSymbolAsync(c_pack, wpack_addr, 408 * sizeof(float), 0,
                            cudaMemcpyDeviceToDevice);

    dim3 g1(K1S, NB), g2(K2S, NB);
    garnet_k1<<<g1, 128>>>(data, num_vertex);

    // PDL launches: Km overlaps K1's tail, K2 overlaps Km
    cudaLaunchAttribute pdlAttr[1];
    pdlAttr[0].id = cudaLaunchAttributeProgrammaticStreamSerialization;
    pdlAttr[0].val.programmaticStreamSerializationAllowed = 1;

    {
        cudaLaunchConfig_t cfg = {};
        cfg.gridDim  = dim3(NB, 1, 1);
        cfg.blockDim = dim3(128, 1, 1);
        cfg.attrs    = pdlAttr;
        cfg.numAttrs = 1;
        cudaLaunchKernelEx(&cfg, garnet_km, W_out);
    }
    {
        cudaLaunchConfig_t cfg = {};
        cfg.gridDim  = dim3(K2S, NB, 1);
        cfg.blockDim = dim3(128, 1, 1);
        cfg.attrs    = pdlAttr;
        cfg.numAttrs = 1;
        cudaLaunchKernelEx(&cfg, garnet_k2, num_vertex, b_out, out);
    }
}

// round 14
// speedup vs baseline: 1.3144x; 1.0095x over previous
#include <cuda_runtime.h>

// GarNet: B=256, V=1024, F=16, P=16, A=8, NF=32
// out[b,v,n] = mask(v) * ( sum_a ew[v,a] * M[b,a,n] + b_out[n] )
//   ew[v,a]  = mask(v) * 2^(-(data[v]·W_s + b_s)[a])
//   agg[a,p] = (1/V) sum_v ew[v,a] * (data[v]·W_flr + b_flr)[p]
//   M[a,n]   = sum_p agg[a,p] * W_out[a*P+p, n]
//
// Kp+copy:          pack small weights -> ONE copy -> __constant__.
// K1 (4x256 x128t): single-wave (lb 128,7); 2 v/thread feat+ew (f32x2,
//                   constant port), ew tile -> TMA bulk store overlapped with
//                   quad-product reduction; LAST block per batch folds in the
//                   Km work (partials -> agg -> M) via atomic-counter tail.
// K2 (8x256 x128t): PDL on K1; f32x2 epilogue, TMA bulk store.

#define NB   256
#define NV   1024
#define NFEA 16
#define NP   16
#define NA   8
#define NOUT 32

#define K1S  4
#define K1V  256
#define K2S  8
#define K2V  128

#define RS   258      // ull stride per pair-row (256 + 2)

__device__ float g_ew[NB * NV * NA];          // 8 MB
__device__ float g_part[NB * K1S * 128];      // 512 KB
__device__ float g_M[NB * NA * NOUT];         // 256 KB
__device__ float g_wpack[408];
__device__ unsigned int g_cnt[NB];            // zero-init; reset by tail block

// packed weights: [0,256) W_flr, [256,384) W_s, [384,400) b_flr, [400,408) b_s
__constant__ __align__(16) float c_pack[408];

#define FMA_F32X2(d, a, b, c) \
    asm("fma.rn.f32x2 %0, %1, %2, %3;" : "=l"(d) : "l"(a), "l"(b), "l"(c))
#define PACK2_SAME(out, x) \
    asm("mov.b64 %0, {%1, %1};" : "=l"(out) : "r"(__float_as_uint(x)))
#define PACK2(out, lo, hi) \
    asm("mov.b64 %0, {%1, %2};" : "=l"(out) : "r"(__float_as_uint(lo)), "r"(__float_as_uint(hi)))
#define UNPACK2(lo, hi, in) \
    asm("mov.b64 {%0, %1}, %2;" : "=r"(lo), "=r"(hi) : "l"(in))

#define BULK_S2G(gptr, saddr, bytes) \
    asm volatile("cp.async.bulk.global.shared::cta.bulk_group [%0], [%1], %2;" \
                 :: "l"(gptr), "r"(saddr), "r"(bytes) : "memory")
#define BULK_COMMIT() \
    asm volatile("cp.async.bulk.commit_group;" ::: "memory")
#define BULK_WAIT0() \
    asm volatile("cp.async.bulk.wait_group 0;" ::: "memory")
#define FENCE_ASYNC() \
    asm volatile("fence.proxy.async.shared::cta;" ::: "memory")

// ==================== Kp: pack weights into staging ====================
__global__ void __launch_bounds__(128)
garnet_kp(const float* __restrict__ W_flr,
          const float* __restrict__ W_s,
          const float* __restrict__ b_flr,
          const float* __restrict__ b_s)
{
    const int t = threadIdx.x;
    g_wpack[t]       = W_flr[t];
    g_wpack[t + 128] = W_flr[t + 128];
    g_wpack[t + 256] = W_s[t];
    if (t < 16) g_wpack[384 + t] = b_flr[t];
    if (t < 8)  g_wpack[400 + t] = b_s[t];
}

// ==================== K1 (+ fused Km tail) ====================
__global__ void __launch_bounds__(128, 7)
garnet_k1(const float* __restrict__ data,
          const int*   __restrict__ num_vertex,
          const float* __restrict__ W_out)
{
    __shared__ __align__(16) unsigned long long red2[12 * RS];
    __shared__ __align__(16) unsigned long long comb[32 * 8];   // also agg_sh
    __shared__ __align__(16) float4 ewt[K1V * 2];               // 8KB ew tile
    __shared__ int s_tail;

    float* agg_sh = reinterpret_cast<float*>(comb);

    const int t = threadIdx.x;
    const int s = blockIdx.x;      // 0..3
    const int b = blockIdx.y;
    const int v0 = s * K1V + t;
    const int v1 = v0 + 128;

    const float4* d40 = reinterpret_cast<const float4*>(data) + ((size_t)b * NV + v0) * 4;
    const float4* d41 = reinterpret_cast<const float4*>(data) + ((size_t)b * NV + v1) * 4;

    const ulonglong2* Wf2 = reinterpret_cast<const ulonglong2*>(c_pack);
    const ulonglong2* Ws2 = reinterpret_cast<const ulonglong2*>(c_pack + 256);
    const unsigned long long* bf2 = reinterpret_cast<const unsigned long long*>(c_pack + 384);
    const unsigned long long* bs2 = reinterpret_cast<const unsigned long long*>(c_pack + 400);

    unsigned long long f2a[8], f2b[8], sd2a[4], sd2b[4];
    #pragma unroll
    for (int j = 0; j < 8; ++j) { f2a[j] = bf2[j]; f2b[j] = bf2[j]; }
    #pragma unroll
    for (int j = 0; j < 4; ++j) { sd2a[j] = bs2[j]; sd2b[j] = bs2[j]; }

    const int nv = num_vertex[b];

    #pragma unroll
    for (int c = 0; c < 2; ++c) {
        float4 qa0 = d40[c*2+0], qa1 = d40[c*2+1];
        float4 qb0 = d41[c*2+0], qb1 = d41[c*2+1];
        float xa[8] = {qa0.x,qa0.y,qa0.z,qa0.w, qa1.x,qa1.y,qa1.z,qa1.w};
        float xb[8] = {qb0.x,qb0.y,qb0.z,qb0.w, qb1.x,qb1.y,qb1.z,qb1.w};

        #pragma unroll
        for (int kk = 0; kk < 8; ++kk) {
            const int k = c * 8 + kk;
            unsigned long long xpa, xpb;
            PACK2_SAME(xpa, xa[kk]);
            PACK2_SAME(xpb, xb[kk]);
            const ulonglong2 w0 = Wf2[k*4+0], w1 = Wf2[k*4+1];
            const ulonglong2 w2 = Wf2[k*4+2], w3 = Wf2[k*4+3];
            FMA_F32X2(f2a[0], xpa, w0.x, f2a[0]);  FMA_F32X2(f2b[0], xpb, w0.x, f2b[0]);
            FMA_F32X2(f2a[1], xpa, w0.y, f2a[1]);  FMA_F32X2(f2b[1], xpb, w0.y, f2b[1]);
            FMA_F32X2(f2a[2], xpa, w1.x, f2a[2]);  FMA_F32X2(f2b[2], xpb, w1.x, f2b[2]);
            FMA_F32X2(f2a[3], xpa, w1.y, f2a[3]);  FMA_F32X2(f2b[3], xpb, w1.y, f2b[3]);
            FMA_F32X2(f2a[4], xpa, w2.x, f2a[4]);  FMA_F32X2(f2b[4], xpb, w2.x, f2b[4]);
            FMA_F32X2(f2a[5], xpa, w2.y, f2a[5]);  FMA_F32X2(f2b[5], xpb, w2.y, f2b[5]);
            FMA_F32X2(f2a[6], xpa, w3.x, f2a[6]);  FMA_F32X2(f2b[6], xpb, w3.x, f2b[6]);
            FMA_F32X2(f2a[7], xpa, w3.y, f2a[7]);  FMA_F32X2(f2b[7], xpb, w3.y, f2b[7]);
            const ulonglong2 u0 = Ws2[k*2+0], u1 = Ws2[k*2+1];
            FMA_F32X2(sd2a[0], xpa, u0.x, sd2a[0]);  FMA_F32X2(sd2b[0], xpb, u0.x, sd2b[0]);
            FMA_F32X2(sd2a[1], xpa, u0.y, sd2a[1]);  FMA_F32X2(sd2b[1], xpb, u0.y, sd2b[1]);
            FMA_F32X2(sd2a[2], xpa, u1.x, sd2a[2]);  FMA_F32X2(sd2b[2], xpb, u1.x, sd2b[2]);
            FMA_F32X2(sd2a[3], xpa, u1.y, sd2a[3]);  FMA_F32X2(sd2b[3], xpb, u1.y, sd2b[3]);
        }
    }

    // ew = mask * 2^(-dist); stage to smem tile + reduction rows
    {
        const bool ma = (v0 < nv), mb = (v1 < nv);
        float ewa[8], ewb[8];
        #pragma unroll
        for (int j = 0; j < 4; ++j) {
            unsigned int lo, hi;
            UNPACK2(lo, hi, sd2a[j]);
            ewa[2*j]   = ma ? exp2f(-__uint_as_float(lo)) : 0.0f;
            ewa[2*j+1] = ma ? exp2f(-__uint_as_float(hi)) : 0.0f;
            UNPACK2(lo, hi, sd2b[j]);
            ewb[2*j]   = mb ? exp2f(-__uint_as_float(lo)) : 0.0f;
            ewb[2*j+1] = mb ? exp2f(-__uint_as_float(hi)) : 0.0f;
        }

        ewt[t * 2]             = make_float4(ewa[0], ewa[1], ewa[2], ewa[3]);
        ewt[t * 2 + 1]         = make_float4(ewa[4], ewa[5], ewa[6], ewa[7]);
        ewt[(t + 128) * 2]     = make_float4(ewb[0], ewb[1], ewb[2], ewb[3]);
        ewt[(t + 128) * 2 + 1] = make_float4(ewb[4], ewb[5], ewb[6], ewb[7]);

        #pragma unroll
        for (int j = 0; j < 4; ++j) {
            unsigned long long ea, eb;
            PACK2(ea, ewa[2*j], ewa[2*j+1]);
            PACK2(eb, ewb[2*j], ewb[2*j+1]);
            red2[j * RS + t]       = ea;
            red2[j * RS + t + 128] = eb;
        }
        #pragma unroll
        for (int j = 0; j < 8; ++j) {
            red2[(4 + j) * RS + t]       = f2a[j];
            red2[(4 + j) * RS + t + 128] = f2b[j];
        }
    }
    __syncthreads();

    // TMA bulk store of ew tile — overlaps the reduction below
    if (t == 0) {
        FENCE_ASYNC();
        unsigned int saddr = (unsigned int)__cvta_generic_to_shared(ewt);
        float* gdst = g_ew + ((size_t)b * NV + s * K1V) * NA;
        BULK_S2G(gdst, saddr, K1V * NA * 4);
        BULK_COMMIT();
    }

    // quad reduction
    {
        const int q  = t >> 2;
        const int vs = t & 3;
        const int apair = q >> 3;
        const int ppair = q & 7;
        const unsigned long long* er = &red2[apair * RS];
        const unsigned long long* fr = &red2[(4 + ppair) * RS];

        unsigned long long acc0 = 0ull, acc1 = 0ull;
        #pragma unroll
        for (int i = 0; i < 32; ++i) {
            const int col = vs * 2 + i * 8;
            const ulonglong2 e2  = *reinterpret_cast<const ulonglong2*>(er + col);
            const ulonglong2 ff2 = *reinterpret_cast<const ulonglong2*>(fr + col);
            unsigned int lo, hi;
            unsigned long long d0, d1;
            UNPACK2(lo, hi, e2.x);
            PACK2_SAME(d0, __uint_as_float(lo));
            PACK2_SAME(d1, __uint_as_float(hi));
            FMA_F32X2(acc0, d0, ff2.x, acc0);
            FMA_F32X2(acc1, d1, ff2.x, acc1);
            UNPACK2(lo, hi, e2.y);
            PACK2_SAME(d0, __uint_as_float(lo));
            PACK2_SAME(d1, __uint_as_float(hi));
            FMA_F32X2(acc0, d0, ff2.y, acc0);
            FMA_F32X2(acc1, d1, ff2.y, acc1);
        }
        comb[q * 8 + vs * 2 + 0] = acc0;
        comb[q * 8 + vs * 2 + 1] = acc1;
    }
    __syncthreads();

    // final combine -> g_part
    {
        const int a = t >> 4, p = t & 15;
        const int qq = (a >> 1) * 8 + (p >> 1);
        const float* cf = reinterpret_cast<const float*>(comb);
        float ssum = 0.f;
        #pragma unroll
        for (int vs = 0; vs < 4; ++vs)
            ssum += cf[(qq * 8 + vs * 2 + (a & 1)) * 2 + (p & 1)];
        g_part[((size_t)b * K1S + s) * 128 + t] = ssum;
    }
    __syncthreads();   // all partial writes issued; comb reusable below

    // ---- fused Km tail: last-arriving block of batch b builds M ----
    if (t == 0) {
        __threadfence();                              // publish g_part
        unsigned int r = atomicAdd(&g_cnt[b], 1u);
        s_tail = (r == K1S - 1) ? 1 : 0;
    }
    __syncthreads();

    if (s_tail) {
        __threadfence();                              // see other blocks' g_part
        float acc = 0.f;
        #pragma unroll
        for (int sp = 0; sp < K1S; ++sp)
            acc += g_part[((size_t)b * K1S + sp) * 128 + t];
        agg_sh[t] = acc * (1.0f / (float)NV);
        __syncthreads();

        #pragma unroll
        for (int e = t; e < 256; e += 128) {
            const int a = e >> 5, n = e & 31;
            float mm = 0.f;
            #pragma unroll
            for (int p = 0; p < 16; ++p)
                mm += agg_sh[a * 16 + p] * W_out[(a * 16 + p) * 32 + n];
            g_M[b * 256 + e] = mm;
        }
        if (t == 0) g_cnt[b] = 0;                     // reset for graph replay
    }

    if (t == 0) BULK_WAIT0();
}

// ==================== K2 (PDL: independent prologue before grid sync) ========
__global__ void __launch_bounds__(128)
garnet_k2(const int*   __restrict__ num_vertex,
          const float* __restrict__ b_out,
          float*       __restrict__ out)
{
    __shared__ __align__(16) ulonglong2 tile2[K2V * NOUT / 4];  // 16KB out tile
    __shared__ float4 ew4_sh[K2V * 2];
    __shared__ float4 M4_sh[64];

    const int t  = threadIdx.x;
    const int s  = blockIdx.x;
    const int b  = blockIdx.y;
    const int ng = t & 7;
    const int vl = t >> 3;

    // pre-sync: inputs independent of K1
    const int nv = num_vertex[b];
    const float4 bo = reinterpret_cast<const float4*>(b_out)[ng];
    unsigned long long bo2lo, bo2hi;
    PACK2(bo2lo, bo.x, bo.y);
    PACK2(bo2hi, bo.z, bo.w);

    cudaGridDependencySynchronize();   // wait for K1 (incl. fused M tail)

    {
        const float4* src = reinterpret_cast<const float4*>(g_ew)
                          + ((size_t)b * NV + s * K2V) * 2;
        ew4_sh[t]       = src[t];
        ew4_sh[t + 128] = src[t + 128];
        if (t < 64)
            M4_sh[t] = reinterpret_cast<const float4*>(g_M + b * 256)[t];
    }
    __syncthreads();

    ulonglong2 Mr2[8];
    {
        const ulonglong2* M2 = reinterpret_cast<const ulonglong2*>(M4_sh);
        #pragma unroll
        for (int a = 0; a < 8; ++a) Mr2[a] = M2[a * 8 + ng];
    }

    const ulonglong2 z2 = make_ulonglong2(0ull, 0ull);

    #pragma unroll
    for (int k = 0; k < 8; ++k) {
        const int v = vl + k * 16;
        const float4 e0 = ew4_sh[v * 2];
        const float4 e1 = ew4_sh[v * 2 + 1];
        const float ew[8] = {e0.x, e0.y, e0.z, e0.w, e1.x, e1.y, e1.z, e1.w};

        unsigned long long acc0 = bo2lo, acc1 = bo2hi;
        #pragma unroll
        for (int a = 0; a < 8; ++a) {
            unsigned long long ep;
            PACK2_SAME(ep, ew[a]);
            FMA_F32X2(acc0, ep, Mr2[a].x, acc0);
            FMA_F32X2(acc1, ep, Mr2[a].y, acc1);
        }

        tile2[t + k * 128] = (s * K2V + v < nv) ? make_ulonglong2(acc0, acc1) : z2;
    }
    __syncthreads();

    if (t == 0) {
        FENCE_ASYNC();
        unsigned int saddr = (unsigned int)__cvta_generic_to_shared(tile2);
        float* gdst = out + ((size_t)b * NV + s * K2V) * NOUT;
        BULK_S2G(gdst, saddr, K2V * NOUT * 4);
        BULK_COMMIT();
        BULK_WAIT0();
    }
}

extern "C" void kernel_launch(void* const* d_in, const int* in_sizes, int n_in,
                              void* d_out, int out_size)
{
    const float* data       = (const float*)d_in[0];
    const int*   num_vertex = (const int*)  d_in[1];
    const float* W_flr      = (const float*)d_in[2];
    const float* b_flr      = (const float*)d_in[3];
    const float* W_s        = (const float*)d_in[4];
    const float* b_s        = (const float*)d_in[5];
    const float* W_out      = (const float*)d_in[6];
    const float* b_out      = (const float*)d_in[7];
    float*       out        = (float*)d_out;

    (void)in_sizes; (void)n_in; (void)out_size;

    garnet_kp<<<1, 128>>>(W_flr, W_s, b_flr, b_s);

    void* wpack_addr = nullptr;
    cudaGetSymbolAddress(&wpack_addr, g_wpack);
    cudaMemcpyToSymbolAsync(c_pack, wpack_addr, 408 * sizeof(float), 0,
                            cudaMemcpyDeviceToDevice);

    dim3 g1(K1S, NB), g2(K2S, NB);
    garnet_k1<<<g1, 128>>>(data, num_vertex, W_out);

    // PDL: K2 overlaps K1's tail
    cudaLaunchAttribute pdlAttr[1];
    pdlAttr[0].id = cudaLaunchAttributeProgrammaticStreamSerialization;
    pdlAttr[0].val.programmaticStreamSerializationAllowed = 1;

    cudaLaunchConfig_t cfg = {};
    cfg.gridDim  = g2;
    cfg.blockDim = dim3(128, 1, 1);
    cfg.attrs    = pdlAttr;
    cfg.numAttrs = 1;
    cudaLaunchKernelEx(&cfg, garnet_k2, num_vertex, b_out, out);
}